// round 8
// baseline (speedup 1.0000x reference)
#include <cuda_runtime.h>
#include <cstdint>

// Problem shape (fixed by the dataset):
//   x:       (4, 2048, 4096) fp32  -> M=8192, K=4096 row-major
//   qweight: (512, 11008)   int32  -> 8 int4 nibbles per int32 along K
//   scales:  (32, 11008)    fp32   -> per-group(128) per-out-channel
//   out:     (4, 2048, 11008) fp32
static constexpr int M_DIM = 8192;
static constexpr int K_DIM = 4096;
static constexpr int N_DIM = 11008;

static constexpr int BM = 128;
static constexpr int BN = 128;
static constexpr int BK = 32;
static constexpr int NTH = 192;              // warps 0-3 consumers, 4-5 producers
static constexpr int K_ITERS = K_DIM / BK;   // 128
static constexpr int STAGES = 3;

// Both tiles stored "outer x k" with stride 36 floats (144B rows):
//   As[m][k], Bs[n][k]; frag LDS bank = (4g + t) % 32 -> conflict free.
static constexpr int STRIDE = BK + 4;              // 36
static constexpr int A_ST_F = BM * STRIDE;         // 4608 floats (18432 B)
static constexpr int B_ST_F = BN * STRIDE;         // 4608 floats
static constexpr int STAGE_F = A_ST_F + B_ST_F;    // 9216 floats (36864 B)
// smem: [0,48) mbarriers, data at float offset 32 (byte 128)
static constexpr int SMEM_BYTES = 128 + STAGES * STAGE_F * 4;  // 110720

__device__ __forceinline__ uint32_t smem_u32(const void* p) {
    uint32_t a;
    asm("{ .reg .u64 t; cvta.to.shared.u64 t, %1; cvt.u32.u64 %0, t; }"
        : "=r"(a) : "l"(p));
    return a;
}
__device__ __forceinline__ void cp16(uint32_t dst, const void* src) {
    asm volatile("cp.async.cg.shared.global [%0], [%1], 16;"
                 :: "r"(dst), "l"(src));
}
__device__ __forceinline__ void mbar_init(uint32_t m, uint32_t cnt) {
    asm volatile("mbarrier.init.shared.b64 [%0], %1;" :: "r"(m), "r"(cnt) : "memory");
}
__device__ __forceinline__ void mbar_arrive(uint32_t m) {
    asm volatile("mbarrier.arrive.shared.b64 _, [%0];" :: "r"(m) : "memory");
}
__device__ __forceinline__ void cp_arrive(uint32_t m) {
    asm volatile("cp.async.mbarrier.arrive.shared.b64 [%0];" :: "r"(m) : "memory");
}
__device__ __forceinline__ void mbar_wait(uint32_t mbar, uint32_t parity) {
    uint32_t done;
    asm volatile(
        "{\n\t"
        ".reg .pred p;\n\t"
        "mbarrier.try_wait.parity.acquire.cta.shared::cta.b64 p, [%1], %2;\n\t"
        "selp.b32 %0, 1, 0, p;\n\t"
        "}"
        : "=r"(done) : "r"(mbar), "r"(parity) : "memory");
    if (!done) {
        asm volatile(
            "{\n\t"
            ".reg .pred P1;\n\t"
            "WL_%=:\n\t"
            "mbarrier.try_wait.parity.acquire.cta.shared::cta.b64 P1, [%0], %1, 0x989680;\n\t"
            "@P1 bra.uni WD_%=;\n\t"
            "bra.uni WL_%=;\n\t"
            "WD_%=:\n\t"
            "}"
            :: "r"(mbar), "r"(parity) : "memory");
    }
}

// fp32 -> tf32 round-to-nearest in the integer domain
__device__ __forceinline__ float rn_tf32(float w) {
    return __uint_as_float(__float_as_uint(w) + 0x1000u);
}
__device__ __forceinline__ void mma_tf32(float c[4],
                                         uint32_t a0, uint32_t a1,
                                         uint32_t a2, uint32_t a3,
                                         uint32_t b0, uint32_t b1)
{
    asm volatile(
        "mma.sync.aligned.m16n8k8.row.col.f32.tf32.tf32.f32 "
        "{%0,%1,%2,%3}, {%4,%5,%6,%7}, {%8,%9}, {%0,%1,%2,%3};\n"
        : "+f"(c[0]), "+f"(c[1]), "+f"(c[2]), "+f"(c[3])
        : "r"(a0), "r"(a1), "r"(a2), "r"(a3), "r"(b0), "r"(b1));
}

__global__ __launch_bounds__(NTH, 2)
void int4_gemm_ws_kernel(const float* __restrict__ X,
                         const int*   __restrict__ QW,
                         const float* __restrict__ SC,
                         float*       __restrict__ C)
{
    extern __shared__ float smem[];
    const uint32_t sb = smem_u32(smem);
    float* data = smem + 32;   // byte offset 128

    const int tid  = threadIdx.x;
    const int wid  = tid >> 5;
    const int lane = tid & 31;
    const int g    = lane >> 2;
    const int t    = lane & 3;

    const int m0 = blockIdx.y * BM;
    const int n0 = blockIdx.x * BN;

    // mbarriers: full[s] = sb + 16s, empty[s] = sb + 16s + 8
    if (tid == 0) {
        #pragma unroll
        for (int s = 0; s < STAGES; s++) {
            mbar_init(sb + 16 * s, 64);        // full: 64 producer arrives (+cp)
            mbar_init(sb + 16 * s + 8, 128);   // empty: 128 consumer arrives
        }
    }
    __syncthreads();

    if (wid < 4) {
        // ================= CONSUMERS: 4 warps, 64x64 tiles =================
        const int wm = wid >> 1;
        const int wn = wid & 1;

        float acc[4][8][4];
        #pragma unroll
        for (int i = 0; i < 4; i++)
            #pragma unroll
            for (int j = 0; j < 8; j++)
                #pragma unroll
                for (int r = 0; r < 4; r++) acc[i][j][r] = 0.0f;

        int st = 0, ph = 0;
        for (int iter = 0; iter < K_ITERS; iter++) {
            mbar_wait(sb + 16 * st, ph);

            const float* As = data + st * STAGE_F;
            const float* Bs = As + A_ST_F;
            const float* Ap = As + (wm * 64 + g) * STRIDE + t;
            const float* Bp = Bs + (wn * 64 + g) * STRIDE + t;

            #pragma unroll
            for (int kk = 0; kk < 4; kk++) {
                const int kb = kk * 8;
                uint32_t a[4][4];
                #pragma unroll
                for (int i = 0; i < 4; i++) {
                    const float* ar = Ap + i * 16 * STRIDE + kb;
                    a[i][0] = __float_as_uint(ar[0]);
                    a[i][1] = __float_as_uint(ar[8 * STRIDE]);
                    a[i][2] = __float_as_uint(ar[4]);
                    a[i][3] = __float_as_uint(ar[8 * STRIDE + 4]);
                }
                uint32_t b0 = __float_as_uint(Bp[kb]);
                uint32_t b1 = __float_as_uint(Bp[kb + 4]);
                #pragma unroll
                for (int j = 0; j < 8; j++) {
                    uint32_t nb0 = 0, nb1 = 0;
                    if (j < 7) {
                        nb0 = __float_as_uint(Bp[(j + 1) * 8 * STRIDE + kb]);
                        nb1 = __float_as_uint(Bp[(j + 1) * 8 * STRIDE + kb + 4]);
                    }
                    #pragma unroll
                    for (int i = 0; i < 4; i++)
                        mma_tf32(acc[i][j], a[i][0], a[i][1], a[i][2], a[i][3],
                                 b0, b1);
                    b0 = nb0; b1 = nb1;
                }
            }

            mbar_arrive(sb + 16 * st + 8);   // empty
            if (++st == STAGES) { st = 0; ph ^= 1; }
        }

        // ---- epilogue -------------------------------------------------------
        #pragma unroll
        for (int i = 0; i < 4; i++) {
            int row = m0 + wm * 64 + i * 16 + g;
            #pragma unroll
            for (int j = 0; j < 8; j++) {
                int col = n0 + wn * 64 + j * 8 + 2 * t;
                *reinterpret_cast<float2*>(&C[(size_t)row * N_DIM + col]) =
                    make_float2(acc[i][j][0], acc[i][j][1]);
                *reinterpret_cast<float2*>(&C[(size_t)(row + 8) * N_DIM + col]) =
                    make_float2(acc[i][j][2], acc[i][j][3]);
            }
        }
    } else {
        // ================= PRODUCERS: 2 warps (64 threads) ==================
        const int ptid = tid - 128;          // 0..63
        const float* Xr0 = X + (size_t)(m0 + ptid) * K_DIM;
        const float* Xr1 = X + (size_t)(m0 + ptid + 64) * K_DIM;
        const int*   Q0  = QW + n0 + ptid;
        const int*   Q1  = Q0 + 64;
        const float* S0  = SC + n0 + ptid;
        const float* S1  = S0 + 64;

        int   q0[4], q1[4];
        float s0v, s1v;
        #pragma unroll
        for (int qr = 0; qr < 4; qr++) {
            q0[qr] = Q0[(size_t)qr * N_DIM];
            q1[qr] = Q1[(size_t)qr * N_DIM];
        }
        s0v = S0[0];
        s1v = S1[0];

        int st = 0, ph = 1;   // flipped phase: first-lap empty waits pass
        for (int iter = 0; iter < K_ITERS; iter++) {
            mbar_wait(sb + 16 * st + 8, ph);   // empty

            const uint32_t stb = sb + 128 + (uint32_t)st * (STAGE_F * 4);

            // ---- A tile via cp.async: rows ptid, ptid+64 (32 floats each) --
            {
                const float* xa = Xr0 + iter * BK;
                const uint32_t d0 = stb + (uint32_t)ptid * (STRIDE * 4);
                #pragma unroll
                for (int c = 0; c < 8; c++) cp16(d0 + c * 16u, xa + c * 4);
                const float* xb = Xr1 + iter * BK;
                const uint32_t d1 = stb + (uint32_t)(ptid + 64) * (STRIDE * 4);
                #pragma unroll
                for (int c = 0; c < 8; c++) cp16(d1 + c * 16u, xb + c * 4);
                cp_arrive(sb + 16 * st);       // full (on cp completion)
            }

            // ---- prefetch next iter's qweights/scales ----------------------
            int   nq0[4], nq1[4];
            float ns0 = s0v, ns1 = s1v;
            if (iter + 1 < K_ITERS) {
                const int krow = (iter + 1) * 4;
                #pragma unroll
                for (int qr = 0; qr < 4; qr++) {
                    nq0[qr] = Q0[(size_t)(krow + qr) * N_DIM];
                    nq1[qr] = Q1[(size_t)(krow + qr) * N_DIM];
                }
                ns0 = S0[(size_t)((iter + 1) >> 2) * N_DIM];
                ns1 = S1[(size_t)((iter + 1) >> 2) * N_DIM];
            }

            // ---- dequant current B tile (n-major, STS.128) ------------------
            {
                float* Bst = data + st * STAGE_F + A_ST_F;
                #pragma unroll
                for (int h = 0; h < 2; h++) {
                    const int col = ptid + h * 64;
                    const float s = h ? s1v : s0v;
                    float* bp = Bst + col * STRIDE;
                    #pragma unroll
                    for (int qr = 0; qr < 4; qr++) {
                        const uint32_t q = (uint32_t)(h ? q1[qr] : q0[qr]);
                        float o[8];
                        #pragma unroll
                        for (int j = 0; j < 8; j++) {
                            float fv = __uint_as_float(
                                0x4B000000u | ((q >> (4 * j)) & 15u));
                            o[j] = rn_tf32((fv - 8388616.0f) * s);
                        }
                        *reinterpret_cast<float4*>(bp + qr * 8) =
                            make_float4(o[0], o[1], o[2], o[3]);
                        *reinterpret_cast<float4*>(bp + qr * 8 + 4) =
                            make_float4(o[4], o[5], o[6], o[7]);
                    }
                }
            }

            mbar_arrive(sb + 16 * st);         // full (release)

            #pragma unroll
            for (int qr = 0; qr < 4; qr++) { q0[qr] = nq0[qr]; q1[qr] = nq1[qr]; }
            s0v = ns0; s1v = ns1;

            if (++st == STAGES) { st = 0; ph ^= 1; }
        }
    }
}

extern "C" void kernel_launch(void* const* d_in, const int* in_sizes, int n_in,
                              void* d_out, int out_size)
{
    const float* x   = (const float*)d_in[0];
    const int*   qw  = (const int*)d_in[1];
    const float* sc  = (const float*)d_in[2];
    float*       out = (float*)d_out;

    cudaFuncSetAttribute(int4_gemm_ws_kernel,
                         cudaFuncAttributeMaxDynamicSharedMemorySize, SMEM_BYTES);

    dim3 grid(N_DIM / BN, M_DIM / BM);  // (86, 64)
    int4_gemm_ws_kernel<<<grid, NTH, SMEM_BYTES>>>(x, qw, sc, out);
}

// round 9
// speedup vs baseline: 1.1912x; 1.1912x over previous
#include <cuda_runtime.h>
#include <cstdint>

// Problem shape (fixed by the dataset):
//   x:       (4, 2048, 4096) fp32  -> M=8192, K=4096 row-major
//   qweight: (512, 11008)   int32  -> 8 int4 nibbles per int32 along K
//   scales:  (32, 11008)    fp32   -> per-group(128) per-out-channel
//   out:     (4, 2048, 11008) fp32
static constexpr int M_DIM = 8192;
static constexpr int K_DIM = 4096;
static constexpr int N_DIM = 11008;

static constexpr int BM = 128;
static constexpr int BN = 256;
static constexpr int BK = 32;
static constexpr int NTH = 512;              // 16 warps: 2(m) x 8(n), tile 64x32
static constexpr int K_ITERS = K_DIM / BK;   // 128

// Both tiles "outer x k", stride 36 floats (144B rows):
//   As[m][k], Bs[n][k]; frag LDS bank = (4g + t) % 32 -> conflict-free.
static constexpr int STRIDE  = BK + 4;             // 36
static constexpr int A_ELEMS = BM * STRIDE;        // 4608 floats / buffer
static constexpr int B_ELEMS = BN * STRIDE;        // 9216 floats / buffer
static constexpr int SMEM_BYTES = 2 * (A_ELEMS + B_ELEMS) * 4;  // 110592

__device__ __forceinline__ uint32_t smem_u32(const void* p) {
    uint32_t a;
    asm("{ .reg .u64 t; cvta.to.shared.u64 t, %1; cvt.u32.u64 %0, t; }"
        : "=r"(a) : "l"(p));
    return a;
}
__device__ __forceinline__ void cp16(uint32_t dst, const void* src) {
    asm volatile("cp.async.cg.shared.global [%0], [%1], 16;"
                 :: "r"(dst), "l"(src));
}
// fp32 -> tf32 round-to-nearest in the integer domain (HMMA reads top 19 bits)
__device__ __forceinline__ float rn_tf32(float w) {
    return __uint_as_float(__float_as_uint(w) + 0x1000u);
}
__device__ __forceinline__ void mma_tf32(float c[4],
                                         uint32_t a0, uint32_t a1,
                                         uint32_t a2, uint32_t a3,
                                         uint32_t b0, uint32_t b1)
{
    asm volatile(
        "mma.sync.aligned.m16n8k8.row.col.f32.tf32.tf32.f32 "
        "{%0,%1,%2,%3}, {%4,%5,%6,%7}, {%8,%9}, {%0,%1,%2,%3};\n"
        : "+f"(c[0]), "+f"(c[1]), "+f"(c[2]), "+f"(c[3])
        : "r"(a0), "r"(a1), "r"(a2), "r"(a3), "r"(b0), "r"(b1));
}

__global__ __launch_bounds__(NTH, 1)
void int4_gemm_tf32_w16_kernel(const float* __restrict__ X,
                               const int*   __restrict__ QW,
                               const float* __restrict__ SC,
                               float*       __restrict__ C)
{
    extern __shared__ float smem[];
    float* Asm = smem;                       // 2 x A_ELEMS
    float* Bsm = smem + 2 * A_ELEMS;         // 2 x B_ELEMS
    const uint32_t As_u32 = smem_u32(Asm);

    const int tid  = threadIdx.x;
    const int wid  = tid >> 5;
    const int lane = tid & 31;
    const int g    = lane >> 2;
    const int t    = lane & 3;
    const int wm   = wid >> 3;               // 0..1
    const int wn   = wid & 7;                // 0..7

    const int m0 = blockIdx.y * BM;
    const int n0 = blockIdx.x * BN;

    // ---- accumulators: warp 64x32 -> 4 x 4 x 4 = 64 regs -------------------
    float acc[4][4][4];
    #pragma unroll
    for (int i = 0; i < 4; i++)
        #pragma unroll
        for (int j = 0; j < 4; j++)
            #pragma unroll
            for (int r = 0; r < 4; r++) acc[i][j][r] = 0.0f;

    // ---- producer mappings ---------------------------------------------------
    // A: thread -> row tid>>2 (0..127), chunk (tid&3)*8 floats -> 2 x cp16
    const int arow   = tid >> 2;
    const int achunk = (tid & 3) * 8;
    const float* Xrow = X + (size_t)(m0 + arow) * K_DIM + achunk;
    const uint32_t a_dst0 = As_u32 + (uint32_t)(arow * STRIDE + achunk) * 4u;

    // B: thread -> column n0 + (tid & 255), k-half (tid >> 8) of the 32-k tile
    const int bcol = tid & 255;
    const int half = tid >> 8;                // 0 or 1 -> qweight rows 2h, 2h+1
    const int*   QWp = QW + n0 + bcol;
    const float* SCp = SC + n0 + bcol;

    int   qv[2];
    float s;

    // ---- prologue: stage + commit tile 0 --------------------------------------
    {
        cp16(a_dst0,       Xrow);
        cp16(a_dst0 + 16u, Xrow + 4);
        asm volatile("cp.async.commit_group;");

        qv[0] = QWp[(size_t)(half * 2)     * N_DIM];
        qv[1] = QWp[(size_t)(half * 2 + 1) * N_DIM];
        s     = SCp[0];

        float* bp = Bsm + bcol * STRIDE + half * 16;
        #pragma unroll
        for (int qq = 0; qq < 2; qq++) {
            const uint32_t q = (uint32_t)qv[qq];
            float o[8];
            #pragma unroll
            for (int j = 0; j < 8; j++) {
                float fv = __uint_as_float(0x4B000000u | ((q >> (4 * j)) & 15u));
                o[j] = rn_tf32((fv - 8388616.0f) * s);
            }
            *reinterpret_cast<float4*>(bp + qq * 8)     = make_float4(o[0], o[1], o[2], o[3]);
            *reinterpret_cast<float4*>(bp + qq * 8 + 4) = make_float4(o[4], o[5], o[6], o[7]);
        }
        asm volatile("cp.async.wait_group 0;" ::: "memory");
        __syncthreads();
    }

    // ---- main loop --------------------------------------------------------------
    for (int iter = 0; iter < K_ITERS; iter++) {
        const int buf = iter & 1;
        const int nb  = buf ^ 1;
        const bool more = (iter + 1 < K_ITERS);

        // stage next tile: A via cp.async, B qwords via LDG into regs
        if (more) {
            const float* xp = Xrow + (iter + 1) * BK;
            const uint32_t ad = a_dst0 + (uint32_t)(nb * A_ELEMS) * 4u;
            cp16(ad,       xp);
            cp16(ad + 16u, xp + 4);
            asm volatile("cp.async.commit_group;");

            const int krow = (iter + 1) * 4 + half * 2;
            qv[0] = QWp[(size_t)krow       * N_DIM];
            qv[1] = QWp[(size_t)(krow + 1) * N_DIM];
            s     = SCp[(size_t)((iter + 1) >> 2) * N_DIM];
        }

        // ---- compute on current buffer ----------------------------------------
        {
            const float* Ap = Asm + buf * A_ELEMS + (wm * 64 + g) * STRIDE + t;
            const float* Bp = Bsm + buf * B_ELEMS + (wn * 32 + g) * STRIDE + t;

            #pragma unroll
            for (int kk = 0; kk < 4; kk++) {
                const int kb = kk * 8;
                uint32_t a[4][4];
                #pragma unroll
                for (int i = 0; i < 4; i++) {
                    const float* ar = Ap + i * 16 * STRIDE + kb;
                    a[i][0] = __float_as_uint(ar[0]);
                    a[i][1] = __float_as_uint(ar[8 * STRIDE]);
                    a[i][2] = __float_as_uint(ar[4]);
                    a[i][3] = __float_as_uint(ar[8 * STRIDE + 4]);
                }
                uint32_t b[4][2];
                #pragma unroll
                for (int j = 0; j < 4; j++) {
                    const float* br = Bp + j * 8 * STRIDE + kb;
                    b[j][0] = __float_as_uint(br[0]);
                    b[j][1] = __float_as_uint(br[4]);
                }
                #pragma unroll
                for (int i = 0; i < 4; i++)
                    #pragma unroll
                    for (int j = 0; j < 4; j++)
                        mma_tf32(acc[i][j], a[i][0], a[i][1], a[i][2], a[i][3],
                                 b[j][0], b[j][1]);
            }
        }

        // ---- dequant next B tile into the other buffer --------------------------
        if (more) {
            float* bp = Bsm + nb * B_ELEMS + bcol * STRIDE + half * 16;
            #pragma unroll
            for (int qq = 0; qq < 2; qq++) {
                const uint32_t q = (uint32_t)qv[qq];
                float o[8];
                #pragma unroll
                for (int j = 0; j < 8; j++) {
                    float fv = __uint_as_float(0x4B000000u | ((q >> (4 * j)) & 15u));
                    o[j] = rn_tf32((fv - 8388616.0f) * s);
                }
                *reinterpret_cast<float4*>(bp + qq * 8)     = make_float4(o[0], o[1], o[2], o[3]);
                *reinterpret_cast<float4*>(bp + qq * 8 + 4) = make_float4(o[4], o[5], o[6], o[7]);
            }
            asm volatile("cp.async.wait_group 0;" ::: "memory");
        }
        __syncthreads();
    }

    // ---- writeback (m16n8k8 C layout) ------------------------------------------
    #pragma unroll
    for (int i = 0; i < 4; i++) {
        int row = m0 + wm * 64 + i * 16 + g;
        #pragma unroll
        for (int j = 0; j < 4; j++) {
            int col = n0 + wn * 32 + j * 8 + 2 * t;
            *reinterpret_cast<float2*>(&C[(size_t)row * N_DIM + col]) =
                make_float2(acc[i][j][0], acc[i][j][1]);
            *reinterpret_cast<float2*>(&C[(size_t)(row + 8) * N_DIM + col]) =
                make_float2(acc[i][j][2], acc[i][j][3]);
        }
    }
}

extern "C" void kernel_launch(void* const* d_in, const int* in_sizes, int n_in,
                              void* d_out, int out_size)
{
    const float* x   = (const float*)d_in[0];
    const int*   qw  = (const int*)d_in[1];
    const float* sc  = (const float*)d_in[2];
    float*       out = (float*)d_out;

    cudaFuncSetAttribute(int4_gemm_tf32_w16_kernel,
                         cudaFuncAttributeMaxDynamicSharedMemorySize, SMEM_BYTES);

    dim3 grid(N_DIM / BN, M_DIM / BM);  // (43, 64)
    int4_gemm_tf32_w16_kernel<<<grid, NTH, SMEM_BYTES>>>(x, qw, sc, out);
}